// round 3
// baseline (speedup 1.0000x reference)
#include <cuda_runtime.h>
#include <cuda_bf16.h>
#include <math.h>

#define Bb   64
#define Tt   200
#define Dd   128
#define Mm   50
#define BT   (Bb*Tt)          // 12800
#define NUMQ 1000

// ---------------- scratch (no allocs allowed) ----------------
__device__ float g_k[BT*Dd];        // k embeddings (needed for f)
__device__ float g_w[BT*Mm];        // softmax weights
__device__ float g_e[BT*Dd];        // erase gate
__device__ float g_a[BT*Dd];        // add vector
__device__ float g_read[BT*Dd];     // read vectors
__device__ float g_eWt[Dd*Dd];      // e_W^T  [d][o]
__device__ float g_aWt[Dd*Dd];      // a_W^T  [d][o]
__device__ float g_fWt[2*Dd*Dd];    // f_W^T  [d(256)][o(128)]

__device__ __forceinline__ float sigmoidf_(float x){ return 1.f/(1.f+expf(-x)); }

// ---------------- K0: transpose weights once per call ----------------
__global__ void k0_transpose(const float* __restrict__ eW,
                             const float* __restrict__ aW, const float* __restrict__ fW){
    int tid = blockIdx.x*blockDim.x + threadIdx.x;
    int nt  = gridDim.x*blockDim.x;
    for (int i=tid; i<Dd*Dd; i+=nt){ int o=i/Dd, d=i%Dd; g_eWt[d*Dd+o]=eW[i]; g_aWt[d*Dd+o]=aW[i]; }
    for (int i=tid; i<Dd*2*Dd; i+=nt){ int o=i/(2*Dd), d=i%(2*Dd); g_fWt[d*Dd+o]=fW[i]; }
}

// ---------------- K1: gather k/v, compute w (softmax), e, a ----------------
// 16 rows per 256-thread block. Warp wid owns rows {2wid, 2wid+1}; lane owns
// 4 consecutive output cols via float4 weight loads.
__global__ __launch_bounds__(256) void k1_gates(
    const int* __restrict__ q, const int* __restrict__ r, const int* __restrict__ pid,
    const float* __restrict__ pid_emb, const float* __restrict__ k_emb,
    const float* __restrict__ v_emb, const float* __restrict__ Mk,
    const float* __restrict__ e_b, const float* __restrict__ a_b)
{
    const int tid  = threadIdx.x;
    const int lane = tid & 31;
    const int wid  = tid >> 5;
    const int row0 = blockIdx.x * 16;

    __shared__ float k_s[16][Dd];
    __shared__ float v_s[16][Dd];
    __shared__ float mk_s[Mm][129];   // padded: conflict-free across m
    __shared__ float wl[16][52];

    // load Mk into smem
    for (int i=tid; i<Mm*Dd; i+=256) mk_s[i/Dd][i%Dd] = Mk[i];

    // gather k/v (+pid emb) for 16 rows
    for (int i=tid; i<16*Dd; i+=256){
        int rr = i >> 7, d = i & 127;
        int row = row0 + rr;
        int qi = q[row], ri = r[row], pi = pid[row];
        float pe = pid_emb[pi*Dd + d];
        float kk = k_emb[qi*Dd + d] + pe;
        float vv = v_emb[(qi + ri*NUMQ)*Dd + d] + pe;
        k_s[rr][d] = kk;
        v_s[rr][d] = vv;
        g_k[row*Dd + d] = kk;
    }
    __syncthreads();

    // ---- w logits: thread = (row, m) pair ----
    for (int p=tid; p<16*Mm; p+=256){
        int rr = p/Mm, m = p - rr*Mm;
        float acc = 0.f;
        #pragma unroll 4
        for (int d=0; d<Dd; d++) acc = fmaf(mk_s[m][d], k_s[rr][d], acc);
        wl[rr][m] = acc;
    }
    __syncthreads();

    // ---- softmax over m: warp wid handles rows 2wid, 2wid+1 ----
    #pragma unroll
    for (int s2=0; s2<2; s2++){
        int rr  = wid*2 + s2;
        int row = row0 + rr;
        float l0 = (lane      < Mm) ? wl[rr][lane]      : -1e30f;
        float l1 = (lane + 32 < Mm) ? wl[rr][lane + 32] : -1e30f;
        float mx = fmaxf(l0, l1);
        #pragma unroll
        for (int o=16; o; o>>=1) mx = fmaxf(mx, __shfl_xor_sync(0xffffffffu, mx, o));
        float e0 = (lane      < Mm) ? expf(l0 - mx) : 0.f;
        float e1 = (lane + 32 < Mm) ? expf(l1 - mx) : 0.f;
        float ss = e0 + e1;
        #pragma unroll
        for (int o=16; o; o>>=1) ss += __shfl_xor_sync(0xffffffffu, ss, o);
        float inv = 1.f / ss;
        if (lane      < Mm) g_w[row*Mm + lane]      = e0 * inv;
        if (lane + 32 < Mm) g_w[row*Mm + lane + 32] = e1 * inv;
    }

    // ---- e / a GEMV: warp = 2 rows, lane = 4 cols (float4 weights) ----
    {
        const float4* eW4 = reinterpret_cast<const float4*>(g_eWt);
        const float4* aW4 = reinterpret_cast<const float4*>(g_aWt);
        const int r0 = wid*2, r1 = r0+1;
        float4 ae0={0,0,0,0}, ae1={0,0,0,0}, aa0={0,0,0,0}, aa1={0,0,0,0};
        #pragma unroll 2
        for (int d=0; d<Dd; d++){
            float4 ew = eW4[d*32 + lane];
            float4 aw = aW4[d*32 + lane];
            float v0 = v_s[r0][d], v1 = v_s[r1][d];
            ae0.x=fmaf(ew.x,v0,ae0.x); ae0.y=fmaf(ew.y,v0,ae0.y); ae0.z=fmaf(ew.z,v0,ae0.z); ae0.w=fmaf(ew.w,v0,ae0.w);
            ae1.x=fmaf(ew.x,v1,ae1.x); ae1.y=fmaf(ew.y,v1,ae1.y); ae1.z=fmaf(ew.z,v1,ae1.z); ae1.w=fmaf(ew.w,v1,ae1.w);
            aa0.x=fmaf(aw.x,v0,aa0.x); aa0.y=fmaf(aw.y,v0,aa0.y); aa0.z=fmaf(aw.z,v0,aa0.z); aa0.w=fmaf(aw.w,v0,aa0.w);
            aa1.x=fmaf(aw.x,v1,aa1.x); aa1.y=fmaf(aw.y,v1,aa1.y); aa1.z=fmaf(aw.z,v1,aa1.z); aa1.w=fmaf(aw.w,v1,aa1.w);
        }
        float4 eb = reinterpret_cast<const float4*>(e_b)[lane];
        float4 ab = reinterpret_cast<const float4*>(a_b)[lane];
        float4* gE = reinterpret_cast<float4*>(g_e);
        float4* gA = reinterpret_cast<float4*>(g_a);
        int rowA = row0 + r0, rowB = row0 + r1;
        float4 o0, o1;
        o0.x=sigmoidf_(ae0.x+eb.x); o0.y=sigmoidf_(ae0.y+eb.y); o0.z=sigmoidf_(ae0.z+eb.z); o0.w=sigmoidf_(ae0.w+eb.w);
        o1.x=sigmoidf_(ae1.x+eb.x); o1.y=sigmoidf_(ae1.y+eb.y); o1.z=sigmoidf_(ae1.z+eb.z); o1.w=sigmoidf_(ae1.w+eb.w);
        gE[rowA*32 + lane] = o0;
        gE[rowB*32 + lane] = o1;
        o0.x=tanhf(aa0.x+ab.x); o0.y=tanhf(aa0.y+ab.y); o0.z=tanhf(aa0.z+ab.z); o0.w=tanhf(aa0.w+ab.w);
        o1.x=tanhf(aa1.x+ab.x); o1.y=tanhf(aa1.y+ab.y); o1.z=tanhf(aa1.z+ab.z); o1.w=tanhf(aa1.w+ab.w);
        gA[rowA*32 + lane] = o0;
        gA[rowB*32 + lane] = o1;
    }
}

// ---------------- K2: sequential scan over T, parallel over (b, d-chunk) ----------------
__global__ __launch_bounds__(256) void k2_scan(const float* __restrict__ Mv0,
                                               float* __restrict__ out_Mv)
{
    const int b    = blockIdx.y;
    const int lane = threadIdx.x & 31;
    const int wg   = threadIdx.x >> 5;          // 0..7
    const int d    = blockIdx.x * 32 + lane;    // 0..127

    float mv[7];
    #pragma unroll
    for (int i=0; i<7; i++){
        int m = wg + 8*i;
        mv[i] = (m < Mm) ? Mv0[m*Dd + d] : 0.f;
    }

    __shared__ float part[2][8][32];

    const float* wb = g_w + (size_t)b*Tt*Mm;
    const float* eb = g_e + (size_t)b*Tt*Dd;
    const float* ab = g_a + (size_t)b*Tt*Dd;
    float*       rb = g_read + (size_t)b*Tt*Dd;

    float e_d = eb[d];
    float a_d = ab[d];
    float wv[7];
    #pragma unroll
    for (int i=0; i<7; i++){
        int m = wg + 8*i;
        wv[i] = (m < Mm) ? wb[m] : 0.f;
    }

    for (int t=0; t<Tt; t++){
        float e_n = 0.f, a_n = 0.f, wn[7];
        if (t+1 < Tt){
            e_n = eb[(t+1)*Dd + d];
            a_n = ab[(t+1)*Dd + d];
            #pragma unroll
            for (int i=0; i<7; i++){
                int m = wg + 8*i;
                wn[i] = (m < Mm) ? wb[(t+1)*Mm + m] : 0.f;
            }
        } else {
            #pragma unroll
            for (int i=0; i<7; i++) wn[i] = 0.f;
        }

        float pr = 0.f;
        #pragma unroll
        for (int i=0; i<7; i++){
            int m = wg + 8*i;
            if (m < Mm) pr = fmaf(wv[i], mv[i], pr);
        }
        part[t & 1][wg][lane] = pr;
        __syncthreads();

        if (wg == 0){
            float rs = 0.f;
            #pragma unroll
            for (int j=0; j<8; j++) rs += part[t & 1][j][lane];
            rb[t*Dd + d] = rs;
        }

        float* outp = out_Mv + ((size_t)(b*(Tt+1) + t) * Mm) * Dd;
        #pragma unroll
        for (int i=0; i<7; i++){
            int m = wg + 8*i;
            if (m < Mm){
                outp[m*Dd + d] = mv[i];
                float we = wv[i] * e_d;
                mv[i] = fmaf(wv[i], a_d, fmaf(-we, mv[i], mv[i]));
            }
        }

        e_d = e_n; a_d = a_n;
        #pragma unroll
        for (int i=0; i<7; i++) wv[i] = wn[i];
    }

    float* outp = out_Mv + ((size_t)(b*(Tt+1) + Tt) * Mm) * Dd;
    #pragma unroll
    for (int i=0; i<7; i++){
        int m = wg + 8*i;
        if (m < Mm) outp[m*Dd + d] = mv[i];
    }
}

// ---------------- K3: f = tanh([read,k] @ fW^T + fb), p = sigmoid(f . pW + pb) ----------------
// 16 rows per 256-thread block, float4 weight loads, warp = 2 rows.
__global__ __launch_bounds__(256) void k3_head(
    const float* __restrict__ f_b, const float* __restrict__ p_W,
    const float* __restrict__ p_b, float* __restrict__ out_p)
{
    const int tid  = threadIdx.x;
    const int lane = tid & 31;
    const int wid  = tid >> 5;
    const int row0 = blockIdx.x * 16;

    __shared__ float cat_s[16][2*Dd];

    // load [read, k] for 16 rows with float4
    {
        const float4* rd4 = reinterpret_cast<const float4*>(g_read);
        const float4* k4  = reinterpret_cast<const float4*>(g_k);
        for (int i=tid; i<16*32; i+=256){
            int rr = i >> 5, s = i & 31;
            int row = row0 + rr;
            reinterpret_cast<float4*>(&cat_s[rr][0])[s]      = rd4[row*32 + s];
            reinterpret_cast<float4*>(&cat_s[rr][Dd])[s]     = k4[row*32 + s];
        }
    }
    __syncthreads();

    const float4* fW4 = reinterpret_cast<const float4*>(g_fWt);
    const int r0 = wid*2, r1 = r0+1;
    float4 ac0={0,0,0,0}, ac1={0,0,0,0};
    #pragma unroll 2
    for (int dd=0; dd<2*Dd; dd++){
        float4 fw = fW4[dd*32 + lane];
        float c0 = cat_s[r0][dd], c1 = cat_s[r1][dd];
        ac0.x=fmaf(fw.x,c0,ac0.x); ac0.y=fmaf(fw.y,c0,ac0.y); ac0.z=fmaf(fw.z,c0,ac0.z); ac0.w=fmaf(fw.w,c0,ac0.w);
        ac1.x=fmaf(fw.x,c1,ac1.x); ac1.y=fmaf(fw.y,c1,ac1.y); ac1.z=fmaf(fw.z,c1,ac1.z); ac1.w=fmaf(fw.w,c1,ac1.w);
    }

    float4 fb = reinterpret_cast<const float4*>(f_b)[lane];
    float4 pw = reinterpret_cast<const float4*>(p_W)[lane];
    float pb  = p_b[0];

    float s0 = pw.x*tanhf(ac0.x+fb.x) + pw.y*tanhf(ac0.y+fb.y)
             + pw.z*tanhf(ac0.z+fb.z) + pw.w*tanhf(ac0.w+fb.w);
    float s1 = pw.x*tanhf(ac1.x+fb.x) + pw.y*tanhf(ac1.y+fb.y)
             + pw.z*tanhf(ac1.z+fb.z) + pw.w*tanhf(ac1.w+fb.w);
    #pragma unroll
    for (int o=16; o; o>>=1){
        s0 += __shfl_xor_sync(0xffffffffu, s0, o);
        s1 += __shfl_xor_sync(0xffffffffu, s1, o);
    }
    if (lane == 0){
        out_p[row0 + r0] = sigmoidf_(s0 + pb);
        out_p[row0 + r1] = sigmoidf_(s1 + pb);
    }
}

// ---------------- launch ----------------
extern "C" void kernel_launch(void* const* d_in, const int* in_sizes, int n_in,
                              void* d_out, int out_size)
{
    const int*   q       = (const int*)  d_in[0];
    const int*   r       = (const int*)  d_in[1];
    const int*   pid     = (const int*)  d_in[2];
    const float* pid_emb = (const float*)d_in[3];
    const float* k_emb   = (const float*)d_in[4];
    const float* v_emb   = (const float*)d_in[5];
    const float* Mk      = (const float*)d_in[6];
    const float* Mv0     = (const float*)d_in[7];
    const float* f_W     = (const float*)d_in[8];
    const float* f_b     = (const float*)d_in[9];
    const float* p_W     = (const float*)d_in[10];
    const float* p_b     = (const float*)d_in[11];
    const float* e_W     = (const float*)d_in[12];
    const float* e_b     = (const float*)d_in[13];
    const float* a_W     = (const float*)d_in[14];
    const float* a_b     = (const float*)d_in[15];

    float* out_p  = (float*)d_out;              // (64, 200)
    float* out_Mv = (float*)d_out + BT;         // (64, 201, 50, 128)

    k0_transpose<<<256, 256>>>(e_W, a_W, f_W);
    k1_gates<<<BT/16, 256>>>(q, r, pid, pid_emb, k_emb, v_emb, Mk, e_b, a_b);
    {
        dim3 grid(4, Bb);
        k2_scan<<<grid, 256>>>(Mv0, out_Mv);
    }
    k3_head<<<BT/16, 256>>>(f_b, p_W, p_b, out_p);
}

// round 4
// speedup vs baseline: 1.0890x; 1.0890x over previous
#include <cuda_runtime.h>
#include <cuda_bf16.h>
#include <math.h>

#define Bb   64
#define Tt   200
#define Dd   128
#define Mm   50
#define BT   (Bb*Tt)          // 12800
#define NUMQ 1000

// ---------------- scratch ----------------
__device__ float g_k[BT*Dd];
__device__ float g_v[BT*Dd];
__device__ float g_w[BT*Mm];
__device__ float g_e[BT*Dd];
__device__ float g_a[BT*Dd];
__device__ float g_read[BT*Dd];
__device__ float g_Wea[Dd*2*Dd];    // [d][o]: o<128 -> e_W^T, o>=128 -> a_W^T
__device__ float g_fWt[2*Dd*Dd];    // [dd(256)][o(128)]

__device__ __forceinline__ float sigmoidf_(float x){ return 1.f/(1.f+expf(-x)); }

// ---------------- K0: transpose weights ----------------
__global__ void k0_transpose(const float* __restrict__ eW,
                             const float* __restrict__ aW, const float* __restrict__ fW){
    int tid = blockIdx.x*blockDim.x + threadIdx.x;
    int nt  = gridDim.x*blockDim.x;
    for (int i=tid; i<Dd*Dd; i+=nt){
        int o=i/Dd, d=i%Dd;
        g_Wea[d*(2*Dd)+o]      = eW[i];
        g_Wea[d*(2*Dd)+Dd+o]   = aW[i];
    }
    for (int i=tid; i<Dd*2*Dd; i+=nt){ int o=i/(2*Dd), d=i%(2*Dd); g_fWt[d*Dd+o]=fW[i]; }
}

// ---------------- K1: gather k/v, w logits + softmax ----------------
__global__ __launch_bounds__(256) void k1_gather(
    const int* __restrict__ q, const int* __restrict__ r, const int* __restrict__ pid,
    const float* __restrict__ pid_emb, const float* __restrict__ k_emb,
    const float* __restrict__ v_emb, const float* __restrict__ Mk)
{
    const int tid  = threadIdx.x;
    const int lane = tid & 31;
    const int wid  = tid >> 5;
    const int row0 = blockIdx.x * 16;

    __shared__ float k_s[16][Dd];
    __shared__ float mk_s[Mm][129];
    __shared__ float wl[16][52];

    for (int i=tid; i<Mm*Dd; i+=256) mk_s[i/Dd][i%Dd] = Mk[i];

    for (int i=tid; i<16*Dd; i+=256){
        int rr = i >> 7, d = i & 127;
        int row = row0 + rr;
        int qi = q[row], ri = r[row], pi = pid[row];
        float pe = pid_emb[pi*Dd + d];
        float kk = k_emb[qi*Dd + d] + pe;
        float vv = v_emb[(qi + ri*NUMQ)*Dd + d] + pe;
        k_s[rr][d] = kk;
        g_k[row*Dd + d] = kk;
        g_v[row*Dd + d] = vv;
    }
    __syncthreads();

    for (int p=tid; p<16*Mm; p+=256){
        int rr = p/Mm, m = p - rr*Mm;
        float acc = 0.f;
        #pragma unroll 4
        for (int d=0; d<Dd; d++) acc = fmaf(mk_s[m][d], k_s[rr][d], acc);
        wl[rr][m] = acc;
    }
    __syncthreads();

    #pragma unroll
    for (int s2=0; s2<2; s2++){
        int rr  = wid*2 + s2;
        int row = row0 + rr;
        float l0 = (lane      < Mm) ? wl[rr][lane]      : -1e30f;
        float l1 = (lane + 32 < Mm) ? wl[rr][lane + 32] : -1e30f;
        float mx = fmaxf(l0, l1);
        #pragma unroll
        for (int o=16; o; o>>=1) mx = fmaxf(mx, __shfl_xor_sync(0xffffffffu, mx, o));
        float e0 = (lane      < Mm) ? expf(l0 - mx) : 0.f;
        float e1 = (lane + 32 < Mm) ? expf(l1 - mx) : 0.f;
        float ss = e0 + e1;
        #pragma unroll
        for (int o=16; o; o>>=1) ss += __shfl_xor_sync(0xffffffffu, ss, o);
        float inv = 1.f / ss;
        if (lane      < Mm) g_w[row*Mm + lane]      = e0 * inv;
        if (lane + 32 < Mm) g_w[row*Mm + lane + 32] = e1 * inv;
    }
}

// ---------------- smem-tiled GEMM: e/a (fused, 256 cols) ----------------
// grid (200, 2): 64 rows x 128 cols per block. 128 threads, 8x8 thread tile.
__global__ __launch_bounds__(128) void k_ea_gemm(const float* __restrict__ e_b,
                                                 const float* __restrict__ a_b)
{
    const int tid = threadIdx.x;
    const int tx  = tid & 15;          // col group (16)
    const int ty  = tid >> 4;          // row group (8)
    const int row0 = blockIdx.x * 64;
    const int cb   = blockIdx.y;       // 0 -> e, 1 -> a

    __shared__ float act_s[32][68];
    __shared__ float w_s[32][128];

    float acc[8][8];
    #pragma unroll
    for (int i=0;i<8;i++)
        #pragma unroll
        for (int j=0;j<8;j++) acc[i][j]=0.f;

    for (int kc=0; kc<Dd; kc+=32){
        // act tile: 64 rows x 32 k, transposed into act_s[kk][row]
        #pragma unroll
        for (int i=0;i<4;i++){
            int lin = tid + i*128;           // 0..511
            int rr  = lin >> 3;              // 0..63
            int kg  = lin & 7;               // 0..7 (float4 group)
            float4 v = *reinterpret_cast<const float4*>(&g_v[(row0+rr)*Dd + kc + kg*4]);
            act_s[kg*4+0][rr]=v.x; act_s[kg*4+1][rr]=v.y; act_s[kg*4+2][rr]=v.z; act_s[kg*4+3][rr]=v.w;
        }
        // w tile: 32 k x 128 cols
        #pragma unroll
        for (int i=0;i<8;i++){
            int lin = tid + i*128;           // 0..1023
            int kk  = lin >> 5;              // 0..31
            int c4  = lin & 31;              // 0..31
            *reinterpret_cast<float4*>(&w_s[kk][c4*4]) =
                *reinterpret_cast<const float4*>(&g_Wea[(kc+kk)*(2*Dd) + cb*Dd + c4*4]);
        }
        __syncthreads();

        #pragma unroll 4
        for (int kk=0; kk<32; kk++){
            float4 a0 = *reinterpret_cast<float4*>(&act_s[kk][ty*8]);
            float4 a1 = *reinterpret_cast<float4*>(&act_s[kk][ty*8+4]);
            float4 w0 = *reinterpret_cast<float4*>(&w_s[kk][tx*8]);
            float4 w1 = *reinterpret_cast<float4*>(&w_s[kk][tx*8+4]);
            float av[8] = {a0.x,a0.y,a0.z,a0.w,a1.x,a1.y,a1.z,a1.w};
            float wv[8] = {w0.x,w0.y,w0.z,w0.w,w1.x,w1.y,w1.z,w1.w};
            #pragma unroll
            for (int i=0;i<8;i++)
                #pragma unroll
                for (int j=0;j<8;j++) acc[i][j] = fmaf(av[i], wv[j], acc[i][j]);
        }
        __syncthreads();
    }

    // epilogue
    const float* bias = (cb==0) ? e_b : a_b;
    float4 b0 = *reinterpret_cast<const float4*>(&bias[tx*8]);
    float4 b1 = *reinterpret_cast<const float4*>(&bias[tx*8+4]);
    float bb[8] = {b0.x,b0.y,b0.z,b0.w,b1.x,b1.y,b1.z,b1.w};
    float* dst = (cb==0) ? g_e : g_a;
    #pragma unroll
    for (int i=0;i<8;i++){
        int row = row0 + ty*8 + i;
        float o[8];
        if (cb==0){
            #pragma unroll
            for (int j=0;j<8;j++) o[j] = sigmoidf_(acc[i][j] + bb[j]);
        } else {
            #pragma unroll
            for (int j=0;j<8;j++) o[j] = tanhf(acc[i][j] + bb[j]);
        }
        *reinterpret_cast<float4*>(&dst[row*Dd + tx*8])   = make_float4(o[0],o[1],o[2],o[3]);
        *reinterpret_cast<float4*>(&dst[row*Dd + tx*8+4]) = make_float4(o[4],o[5],o[6],o[7]);
    }
}

// ---------------- K2: scan (unchanged) ----------------
__global__ __launch_bounds__(256) void k2_scan(const float* __restrict__ Mv0,
                                               float* __restrict__ out_Mv)
{
    const int b    = blockIdx.y;
    const int lane = threadIdx.x & 31;
    const int wg   = threadIdx.x >> 5;
    const int d    = blockIdx.x * 32 + lane;

    float mv[7];
    #pragma unroll
    for (int i=0; i<7; i++){
        int m = wg + 8*i;
        mv[i] = (m < Mm) ? Mv0[m*Dd + d] : 0.f;
    }

    __shared__ float part[2][8][32];

    const float* wb = g_w + (size_t)b*Tt*Mm;
    const float* eb = g_e + (size_t)b*Tt*Dd;
    const float* ab = g_a + (size_t)b*Tt*Dd;
    float*       rb = g_read + (size_t)b*Tt*Dd;

    float e_d = eb[d];
    float a_d = ab[d];
    float wv[7];
    #pragma unroll
    for (int i=0; i<7; i++){
        int m = wg + 8*i;
        wv[i] = (m < Mm) ? wb[m] : 0.f;
    }

    for (int t=0; t<Tt; t++){
        float e_n = 0.f, a_n = 0.f, wn[7];
        if (t+1 < Tt){
            e_n = eb[(t+1)*Dd + d];
            a_n = ab[(t+1)*Dd + d];
            #pragma unroll
            for (int i=0; i<7; i++){
                int m = wg + 8*i;
                wn[i] = (m < Mm) ? wb[(t+1)*Mm + m] : 0.f;
            }
        } else {
            #pragma unroll
            for (int i=0; i<7; i++) wn[i] = 0.f;
        }

        float pr = 0.f;
        #pragma unroll
        for (int i=0; i<7; i++){
            int m = wg + 8*i;
            if (m < Mm) pr = fmaf(wv[i], mv[i], pr);
        }
        part[t & 1][wg][lane] = pr;
        __syncthreads();

        if (wg == 0){
            float rs = 0.f;
            #pragma unroll
            for (int j=0; j<8; j++) rs += part[t & 1][j][lane];
            rb[t*Dd + d] = rs;
        }

        float* outp = out_Mv + ((size_t)(b*(Tt+1) + t) * Mm) * Dd;
        #pragma unroll
        for (int i=0; i<7; i++){
            int m = wg + 8*i;
            if (m < Mm){
                outp[m*Dd + d] = mv[i];
                float we = wv[i] * e_d;
                mv[i] = fmaf(wv[i], a_d, fmaf(-we, mv[i], mv[i]));
            }
        }

        e_d = e_n; a_d = a_n;
        #pragma unroll
        for (int i=0; i<7; i++) wv[i] = wn[i];
    }

    float* outp = out_Mv + ((size_t)(b*(Tt+1) + Tt) * Mm) * Dd;
    #pragma unroll
    for (int i=0; i<7; i++){
        int m = wg + 8*i;
        if (m < Mm) outp[m*Dd + d] = mv[i];
    }
}

// ---------------- smem-tiled GEMM: f + p head ----------------
// grid 200: 64 rows x 128 cols, K=256 ([read | k]). 128 threads, 8x8 tile.
__global__ __launch_bounds__(128) void k_f_gemm(const float* __restrict__ f_b,
                                                const float* __restrict__ p_W,
                                                const float* __restrict__ p_b,
                                                float* __restrict__ out_p)
{
    const int tid = threadIdx.x;
    const int tx  = tid & 15;
    const int ty  = tid >> 4;
    const int row0 = blockIdx.x * 64;

    __shared__ float act_s[32][68];
    __shared__ float w_s[32][128];

    float acc[8][8];
    #pragma unroll
    for (int i=0;i<8;i++)
        #pragma unroll
        for (int j=0;j<8;j++) acc[i][j]=0.f;

    for (int kc=0; kc<2*Dd; kc+=32){
        const float* src = (kc < Dd) ? (g_read + (size_t)row0*Dd + kc)
                                     : (g_k    + (size_t)row0*Dd + (kc - Dd));
        #pragma unroll
        for (int i=0;i<4;i++){
            int lin = tid + i*128;
            int rr  = lin >> 3;
            int kg  = lin & 7;
            float4 v = *reinterpret_cast<const float4*>(&src[rr*Dd + kg*4]);
            act_s[kg*4+0][rr]=v.x; act_s[kg*4+1][rr]=v.y; act_s[kg*4+2][rr]=v.z; act_s[kg*4+3][rr]=v.w;
        }
        #pragma unroll
        for (int i=0;i<8;i++){
            int lin = tid + i*128;
            int kk  = lin >> 5;
            int c4  = lin & 31;
            *reinterpret_cast<float4*>(&w_s[kk][c4*4]) =
                *reinterpret_cast<const float4*>(&g_fWt[(kc+kk)*Dd + c4*4]);
        }
        __syncthreads();

        #pragma unroll 4
        for (int kk=0; kk<32; kk++){
            float4 a0 = *reinterpret_cast<float4*>(&act_s[kk][ty*8]);
            float4 a1 = *reinterpret_cast<float4*>(&act_s[kk][ty*8+4]);
            float4 w0 = *reinterpret_cast<float4*>(&w_s[kk][tx*8]);
            float4 w1 = *reinterpret_cast<float4*>(&w_s[kk][tx*8+4]);
            float av[8] = {a0.x,a0.y,a0.z,a0.w,a1.x,a1.y,a1.z,a1.w};
            float wv[8] = {w0.x,w0.y,w0.z,w0.w,w1.x,w1.y,w1.z,w1.w};
            #pragma unroll
            for (int i=0;i<8;i++)
                #pragma unroll
                for (int j=0;j<8;j++) acc[i][j] = fmaf(av[i], wv[j], acc[i][j]);
        }
        __syncthreads();
    }

    // epilogue: p = sigmoid( sum_col pW[c]*tanh(acc+fb[c]) + pb )
    float4 fb0 = *reinterpret_cast<const float4*>(&f_b[tx*8]);
    float4 fb1 = *reinterpret_cast<const float4*>(&f_b[tx*8+4]);
    float4 pw0 = *reinterpret_cast<const float4*>(&p_W[tx*8]);
    float4 pw1 = *reinterpret_cast<const float4*>(&p_W[tx*8+4]);
    float fbv[8] = {fb0.x,fb0.y,fb0.z,fb0.w,fb1.x,fb1.y,fb1.z,fb1.w};
    float pwv[8] = {pw0.x,pw0.y,pw0.z,pw0.w,pw1.x,pw1.y,pw1.z,pw1.w};

    float rs[8];
    #pragma unroll
    for (int i=0;i<8;i++){
        float s = 0.f;
        #pragma unroll
        for (int j=0;j<8;j++) s = fmaf(pwv[j], tanhf(acc[i][j] + fbv[j]), s);
        rs[i] = s;
    }
    // reduce across tx (16 lanes within same half-warp)
    #pragma unroll
    for (int o=1; o<16; o<<=1){
        #pragma unroll
        for (int i=0;i<8;i++) rs[i] += __shfl_xor_sync(0xffffffffu, rs[i], o);
    }
    if (tx == 0){
        float pb = p_b[0];
        #pragma unroll
        for (int i=0;i<8;i++) out_p[row0 + ty*8 + i] = sigmoidf_(rs[i] + pb);
    }
}

// ---------------- launch ----------------
extern "C" void kernel_launch(void* const* d_in, const int* in_sizes, int n_in,
                              void* d_out, int out_size)
{
    const int*   q       = (const int*)  d_in[0];
    const int*   r       = (const int*)  d_in[1];
    const int*   pid     = (const int*)  d_in[2];
    const float* pid_emb = (const float*)d_in[3];
    const float* k_emb   = (const float*)d_in[4];
    const float* v_emb   = (const float*)d_in[5];
    const float* Mk      = (const float*)d_in[6];
    const float* Mv0     = (const float*)d_in[7];
    const float* f_W     = (const float*)d_in[8];
    const float* f_b     = (const float*)d_in[9];
    const float* p_W     = (const float*)d_in[10];
    const float* p_b     = (const float*)d_in[11];
    const float* e_W     = (const float*)d_in[12];
    const float* e_b     = (const float*)d_in[13];
    const float* a_W     = (const float*)d_in[14];
    const float* a_b     = (const float*)d_in[15];

    float* out_p  = (float*)d_out;              // (64, 200)
    float* out_Mv = (float*)d_out + BT;         // (64, 201, 50, 128)

    k0_transpose<<<256, 256>>>(e_W, a_W, f_W);
    k1_gather<<<BT/16, 256>>>(q, r, pid, pid_emb, k_emb, v_emb, Mk);
    {
        dim3 gea(BT/64, 2);
        k_ea_gemm<<<gea, 128>>>(e_b, a_b);
    }
    {
        dim3 grid(4, Bb);
        k2_scan<<<grid, 256>>>(Mv0, out_Mv);
    }
    k_f_gemm<<<BT/64, 128>>>(f_b, p_W, p_b, out_p);
}

// round 5
// speedup vs baseline: 1.1044x; 1.0141x over previous
#include <cuda_runtime.h>
#include <cuda_bf16.h>
#include <math.h>

#define Bb   64
#define Tt   200
#define Dd   128
#define Mm   50
#define BT   (Bb*Tt)          // 12800
#define NUMQ 1000
#define NC   8                // scan chunks
#define LL   25               // Tt / NC

// ---------------- scratch ----------------
__device__ float g_k[BT*Dd];
__device__ float g_v[BT*Dd];
__device__ float g_w[BT*Mm];
__device__ float g_e[BT*Dd];
__device__ float g_a[BT*Dd];
__device__ float g_read[BT*Dd];
__device__ float g_Wea[Dd*2*Dd];    // [d][o]: o<128 -> e_W^T, o>=128 -> a_W^T
__device__ float g_fWt[2*Dd*Dd];    // [dd(256)][o(128)]
__device__ float g_A[Bb*NC*Mm*Dd];  // chunk affine scale   [b][ci][m][d]
__device__ float g_B[Bb*NC*Mm*Dd];  // chunk affine offset

__device__ __forceinline__ float sigmoidf_(float x){ return 1.f/(1.f+expf(-x)); }

// ---------------- K0: transpose weights ----------------
__global__ void k0_transpose(const float* __restrict__ eW,
                             const float* __restrict__ aW, const float* __restrict__ fW){
    int tid = blockIdx.x*blockDim.x + threadIdx.x;
    int nt  = gridDim.x*blockDim.x;
    for (int i=tid; i<Dd*Dd; i+=nt){
        int o=i/Dd, d=i%Dd;
        g_Wea[d*(2*Dd)+o]      = eW[i];
        g_Wea[d*(2*Dd)+Dd+o]   = aW[i];
    }
    for (int i=tid; i<Dd*2*Dd; i+=nt){ int o=i/(2*Dd), d=i%(2*Dd); g_fWt[d*Dd+o]=fW[i]; }
}

// ---------------- K1: gather k/v, w logits + softmax ----------------
__global__ __launch_bounds__(256) void k1_gather(
    const int* __restrict__ q, const int* __restrict__ r, const int* __restrict__ pid,
    const float* __restrict__ pid_emb, const float* __restrict__ k_emb,
    const float* __restrict__ v_emb, const float* __restrict__ Mk)
{
    const int tid  = threadIdx.x;
    const int lane = tid & 31;
    const int wid  = tid >> 5;
    const int row0 = blockIdx.x * 16;

    __shared__ float k_s[16][Dd];
    __shared__ float mk_s[Mm][129];
    __shared__ float wl[16][52];

    for (int i=tid; i<Mm*Dd; i+=256) mk_s[i/Dd][i%Dd] = Mk[i];

    for (int i=tid; i<16*Dd; i+=256){
        int rr = i >> 7, d = i & 127;
        int row = row0 + rr;
        int qi = q[row], ri = r[row], pi = pid[row];
        float pe = pid_emb[pi*Dd + d];
        float kk = k_emb[qi*Dd + d] + pe;
        float vv = v_emb[(qi + ri*NUMQ)*Dd + d] + pe;
        k_s[rr][d] = kk;
        g_k[row*Dd + d] = kk;
        g_v[row*Dd + d] = vv;
    }
    __syncthreads();

    for (int p=tid; p<16*Mm; p+=256){
        int rr = p/Mm, m = p - rr*Mm;
        float acc = 0.f;
        #pragma unroll 4
        for (int d=0; d<Dd; d++) acc = fmaf(mk_s[m][d], k_s[rr][d], acc);
        wl[rr][m] = acc;
    }
    __syncthreads();

    #pragma unroll
    for (int s2=0; s2<2; s2++){
        int rr  = wid*2 + s2;
        int row = row0 + rr;
        float l0 = (lane      < Mm) ? wl[rr][lane]      : -1e30f;
        float l1 = (lane + 32 < Mm) ? wl[rr][lane + 32] : -1e30f;
        float mx = fmaxf(l0, l1);
        #pragma unroll
        for (int o=16; o; o>>=1) mx = fmaxf(mx, __shfl_xor_sync(0xffffffffu, mx, o));
        float e0 = (lane      < Mm) ? expf(l0 - mx) : 0.f;
        float e1 = (lane + 32 < Mm) ? expf(l1 - mx) : 0.f;
        float ss = e0 + e1;
        #pragma unroll
        for (int o=16; o; o>>=1) ss += __shfl_xor_sync(0xffffffffu, ss, o);
        float inv = 1.f / ss;
        if (lane      < Mm) g_w[row*Mm + lane]      = e0 * inv;
        if (lane + 32 < Mm) g_w[row*Mm + lane + 32] = e1 * inv;
    }
}

// ---------------- smem-tiled GEMM: e/a (fused) ----------------
__global__ __launch_bounds__(128) void k_ea_gemm(const float* __restrict__ e_b,
                                                 const float* __restrict__ a_b)
{
    const int tid = threadIdx.x;
    const int tx  = tid & 15;
    const int ty  = tid >> 4;
    const int row0 = blockIdx.x * 64;
    const int cb   = blockIdx.y;       // 0 -> e, 1 -> a

    __shared__ float act_s[32][68];
    __shared__ float w_s[32][128];

    float acc[8][8];
    #pragma unroll
    for (int i=0;i<8;i++)
        #pragma unroll
        for (int j=0;j<8;j++) acc[i][j]=0.f;

    for (int kc=0; kc<Dd; kc+=32){
        #pragma unroll
        for (int i=0;i<4;i++){
            int lin = tid + i*128;
            int rr  = lin >> 3;
            int kg  = lin & 7;
            float4 v = *reinterpret_cast<const float4*>(&g_v[(row0+rr)*Dd + kc + kg*4]);
            act_s[kg*4+0][rr]=v.x; act_s[kg*4+1][rr]=v.y; act_s[kg*4+2][rr]=v.z; act_s[kg*4+3][rr]=v.w;
        }
        #pragma unroll
        for (int i=0;i<8;i++){
            int lin = tid + i*128;
            int kk  = lin >> 5;
            int c4  = lin & 31;
            *reinterpret_cast<float4*>(&w_s[kk][c4*4]) =
                *reinterpret_cast<const float4*>(&g_Wea[(kc+kk)*(2*Dd) + cb*Dd + c4*4]);
        }
        __syncthreads();

        #pragma unroll 4
        for (int kk=0; kk<32; kk++){
            float4 a0 = *reinterpret_cast<float4*>(&act_s[kk][ty*8]);
            float4 a1 = *reinterpret_cast<float4*>(&act_s[kk][ty*8+4]);
            float4 w0 = *reinterpret_cast<float4*>(&w_s[kk][tx*8]);
            float4 w1 = *reinterpret_cast<float4*>(&w_s[kk][tx*8+4]);
            float av[8] = {a0.x,a0.y,a0.z,a0.w,a1.x,a1.y,a1.z,a1.w};
            float wv[8] = {w0.x,w0.y,w0.z,w0.w,w1.x,w1.y,w1.z,w1.w};
            #pragma unroll
            for (int i=0;i<8;i++)
                #pragma unroll
                for (int j=0;j<8;j++) acc[i][j] = fmaf(av[i], wv[j], acc[i][j]);
        }
        __syncthreads();
    }

    const float* bias = (cb==0) ? e_b : a_b;
    float4 b0 = *reinterpret_cast<const float4*>(&bias[tx*8]);
    float4 b1 = *reinterpret_cast<const float4*>(&bias[tx*8+4]);
    float bb[8] = {b0.x,b0.y,b0.z,b0.w,b1.x,b1.y,b1.z,b1.w};
    float* dst = (cb==0) ? g_e : g_a;
    #pragma unroll
    for (int i=0;i<8;i++){
        int row = row0 + ty*8 + i;
        float o[8];
        if (cb==0){
            #pragma unroll
            for (int j=0;j<8;j++) o[j] = sigmoidf_(acc[i][j] + bb[j]);
        } else {
            #pragma unroll
            for (int j=0;j<8;j++) o[j] = tanhf(acc[i][j] + bb[j]);
        }
        *reinterpret_cast<float4*>(&dst[row*Dd + tx*8])   = make_float4(o[0],o[1],o[2],o[3]);
        *reinterpret_cast<float4*>(&dst[row*Dd + tx*8+4]) = make_float4(o[4],o[5],o[6],o[7]);
    }
}

// ---------------- K2a: per-chunk affine composition (no barriers in loop) ----------------
// grid (4 dsplit, NC, Bb), 256 threads. Thread = (wg -> m-subset of 7, lane -> d).
__global__ __launch_bounds__(256) void k2a_affine()
{
    const int ds   = blockIdx.x;
    const int ci   = blockIdx.y;
    const int b    = blockIdx.z;
    const int tid  = threadIdx.x;
    const int lane = tid & 31;
    const int wg   = tid >> 5;
    const int d    = ds*32 + lane;
    const int t0   = ci * LL;

    __shared__ float w_s[LL][52];
    for (int i=tid; i<LL*Mm; i+=256){
        int tt = i / Mm, m = i - tt*Mm;
        w_s[tt][m] = g_w[((size_t)b*Tt + t0 + tt)*Mm + m];
    }
    __syncthreads();

    float A[7], Bv[7];
    #pragma unroll
    for (int i=0;i<7;i++){ A[i]=1.f; Bv[i]=0.f; }

    const float* eb = g_e + ((size_t)b*Tt + t0)*Dd;
    const float* ab = g_a + ((size_t)b*Tt + t0)*Dd;

    for (int tt=0; tt<LL; tt++){
        float ev = eb[tt*Dd + d];
        float av = ab[tt*Dd + d];
        #pragma unroll
        for (int i=0;i<7;i++){
            int m = wg + 8*i;
            if (m < Mm){
                float wv = w_s[tt][m];
                float c  = fmaf(-wv, ev, 1.f);
                float u  = wv * av;
                A[i]  = c * A[i];
                Bv[i] = fmaf(c, Bv[i], u);
            }
        }
    }

    size_t base = ((size_t)(b*NC + ci)*Mm)*Dd;
    #pragma unroll
    for (int i=0;i<7;i++){
        int m = wg + 8*i;
        if (m < Mm){
            g_A[base + (size_t)m*Dd + d] = A[i];
            g_B[base + (size_t)m*Dd + d] = Bv[i];
        }
    }
}

// ---------------- K2b: sequential chunk-start states -> out_Mv at t = 0,25,...,200 ----------------
__global__ __launch_bounds__(256) void k2b_chunkstart(const float* __restrict__ Mv0,
                                                      float* __restrict__ out_Mv)
{
    const int ds   = blockIdx.x;
    const int b    = blockIdx.y;
    const int tid  = threadIdx.x;
    const int lane = tid & 31;
    const int wg   = tid >> 5;
    const int d    = ds*32 + lane;

    float s[7];
    #pragma unroll
    for (int i=0;i<7;i++){
        int m = wg + 8*i;
        s[i] = (m < Mm) ? Mv0[m*Dd + d] : 0.f;
    }
    // t = 0
    {
        float* outp = out_Mv + ((size_t)(b*(Tt+1)) * Mm) * Dd;
        #pragma unroll
        for (int i=0;i<7;i++){
            int m = wg + 8*i;
            if (m < Mm) outp[(size_t)m*Dd + d] = s[i];
        }
    }
    for (int ci=0; ci<NC; ci++){
        size_t base = ((size_t)(b*NC + ci)*Mm)*Dd;
        #pragma unroll
        for (int i=0;i<7;i++){
            int m = wg + 8*i;
            if (m < Mm){
                float A  = g_A[base + (size_t)m*Dd + d];
                float Bv = g_B[base + (size_t)m*Dd + d];
                s[i] = fmaf(A, s[i], Bv);
            }
        }
        float* outp = out_Mv + ((size_t)(b*(Tt+1) + (ci+1)*LL) * Mm) * Dd;
        #pragma unroll
        for (int i=0;i<7;i++){
            int m = wg + 8*i;
            if (m < Mm) outp[(size_t)m*Dd + d] = s[i];
        }
    }
}

// ---------------- K2c: expand chunks (thread owns all 50 m for one d; no barriers in loop) ----------------
__global__ __launch_bounds__(128) void k2c_expand(float* __restrict__ out_Mv)
{
    const int ci = blockIdx.x;
    const int b  = blockIdx.y;
    const int d  = threadIdx.x;       // 0..127
    const int t0 = ci * LL;

    __shared__ float w_s[LL][52];
    for (int i=d; i<LL*Mm; i+=128){
        int tt = i / Mm, m = i - tt*Mm;
        w_s[tt][m] = g_w[((size_t)b*Tt + t0 + tt)*Mm + m];
    }
    __syncthreads();

    float mv[Mm];
    {
        const float* st = out_Mv + ((size_t)(b*(Tt+1) + t0) * Mm) * Dd;
        #pragma unroll 10
        for (int m=0; m<Mm; m++) mv[m] = st[(size_t)m*Dd + d];
    }

    const float* eb = g_e + ((size_t)b*Tt + t0)*Dd;
    const float* ab = g_a + ((size_t)b*Tt + t0)*Dd;
    float*       rb = g_read + ((size_t)b*Tt + t0)*Dd;

    // tt = 0: read + update, no Mv store (k2b wrote chunk start)
    {
        float ev = eb[d], av = ab[d];
        float racc = 0.f;
        #pragma unroll 10
        for (int m=0; m<Mm; m++){
            float wv = w_s[0][m];
            racc = fmaf(wv, mv[m], racc);
            float we = wv * ev;
            mv[m] = fmaf(wv, av, fmaf(-we, mv[m], mv[m]));
        }
        rb[d] = racc;
    }
    for (int tt=1; tt<LL; tt++){
        float ev = eb[tt*Dd + d], av = ab[tt*Dd + d];
        float* outp = out_Mv + ((size_t)(b*(Tt+1) + t0 + tt) * Mm) * Dd;
        float racc = 0.f;
        #pragma unroll 10
        for (int m=0; m<Mm; m++){
            float wv = w_s[tt][m];
            float s  = mv[m];
            racc = fmaf(wv, s, racc);
            outp[(size_t)m*Dd + d] = s;
            float we = wv * ev;
            mv[m] = fmaf(wv, av, fmaf(-we, s, s));
        }
        rb[tt*Dd + d] = racc;
    }
}

// ---------------- smem-tiled GEMM: f + p head ----------------
__global__ __launch_bounds__(128) void k_f_gemm(const float* __restrict__ f_b,
                                                const float* __restrict__ p_W,
                                                const float* __restrict__ p_b,
                                                float* __restrict__ out_p)
{
    const int tid = threadIdx.x;
    const int tx  = tid & 15;
    const int ty  = tid >> 4;
    const int row0 = blockIdx.x * 64;

    __shared__ float act_s[32][68];
    __shared__ float w_s[32][128];

    float acc[8][8];
    #pragma unroll
    for (int i=0;i<8;i++)
        #pragma unroll
        for (int j=0;j<8;j++) acc[i][j]=0.f;

    for (int kc=0; kc<2*Dd; kc+=32){
        const float* src = (kc < Dd) ? (g_read + (size_t)row0*Dd + kc)
                                     : (g_k    + (size_t)row0*Dd + (kc - Dd));
        #pragma unroll
        for (int i=0;i<4;i++){
            int lin = tid + i*128;
            int rr  = lin >> 3;
            int kg  = lin & 7;
            float4 v = *reinterpret_cast<const float4*>(&src[rr*Dd + kg*4]);
            act_s[kg*4+0][rr]=v.x; act_s[kg*4+1][rr]=v.y; act_s[kg*4+2][rr]=v.z; act_s[kg*4+3][rr]=v.w;
        }
        #pragma unroll
        for (int i=0;i<8;i++){
            int lin = tid + i*128;
            int kk  = lin >> 5;
            int c4  = lin & 31;
            *reinterpret_cast<float4*>(&w_s[kk][c4*4]) =
                *reinterpret_cast<const float4*>(&g_fWt[(kc+kk)*Dd + c4*4]);
        }
        __syncthreads();

        #pragma unroll 4
        for (int kk=0; kk<32; kk++){
            float4 a0 = *reinterpret_cast<float4*>(&act_s[kk][ty*8]);
            float4 a1 = *reinterpret_cast<float4*>(&act_s[kk][ty*8+4]);
            float4 w0 = *reinterpret_cast<float4*>(&w_s[kk][tx*8]);
            float4 w1 = *reinterpret_cast<float4*>(&w_s[kk][tx*8+4]);
            float av[8] = {a0.x,a0.y,a0.z,a0.w,a1.x,a1.y,a1.z,a1.w};
            float wv[8] = {w0.x,w0.y,w0.z,w0.w,w1.x,w1.y,w1.z,w1.w};
            #pragma unroll
            for (int i=0;i<8;i++)
                #pragma unroll
                for (int j=0;j<8;j++) acc[i][j] = fmaf(av[i], wv[j], acc[i][j]);
        }
        __syncthreads();
    }

    float4 fb0 = *reinterpret_cast<const float4*>(&f_b[tx*8]);
    float4 fb1 = *reinterpret_cast<const float4*>(&f_b[tx*8+4]);
    float4 pw0 = *reinterpret_cast<const float4*>(&p_W[tx*8]);
    float4 pw1 = *reinterpret_cast<const float4*>(&p_W[tx*8+4]);
    float fbv[8] = {fb0.x,fb0.y,fb0.z,fb0.w,fb1.x,fb1.y,fb1.z,fb1.w};
    float pwv[8] = {pw0.x,pw0.y,pw0.z,pw0.w,pw1.x,pw1.y,pw1.z,pw1.w};

    float rs[8];
    #pragma unroll
    for (int i=0;i<8;i++){
        float s = 0.f;
        #pragma unroll
        for (int j=0;j<8;j++) s = fmaf(pwv[j], tanhf(acc[i][j] + fbv[j]), s);
        rs[i] = s;
    }
    #pragma unroll
    for (int o=1; o<16; o<<=1){
        #pragma unroll
        for (int i=0;i<8;i++) rs[i] += __shfl_xor_sync(0xffffffffu, rs[i], o);
    }
    if (tx == 0){
        float pb = p_b[0];
        #pragma unroll
        for (int i=0;i<8;i++) out_p[row0 + ty*8 + i] = sigmoidf_(rs[i] + pb);
    }
}

// ---------------- launch ----------------
extern "C" void kernel_launch(void* const* d_in, const int* in_sizes, int n_in,
                              void* d_out, int out_size)
{
    const int*   q       = (const int*)  d_in[0];
    const int*   r       = (const int*)  d_in[1];
    const int*   pid     = (const int*)  d_in[2];
    const float* pid_emb = (const float*)d_in[3];
    const float* k_emb   = (const float*)d_in[4];
    const float* v_emb   = (const float*)d_in[5];
    const float* Mk      = (const float*)d_in[6];
    const float* Mv0     = (const float*)d_in[7];
    const float* f_W     = (const float*)d_in[8];
    const float* f_b     = (const float*)d_in[9];
    const float* p_W     = (const float*)d_in[10];
    const float* p_b     = (const float*)d_in[11];
    const float* e_W     = (const float*)d_in[12];
    const float* e_b     = (const float*)d_in[13];
    const float* a_W     = (const float*)d_in[14];
    const float* a_b     = (const float*)d_in[15];

    float* out_p  = (float*)d_out;              // (64, 200)
    float* out_Mv = (float*)d_out + BT;         // (64, 201, 50, 128)

    k0_transpose<<<256, 256>>>(e_W, a_W, f_W);
    k1_gather<<<BT/16, 256>>>(q, r, pid, pid_emb, k_emb, v_emb, Mk);
    {
        dim3 gea(BT/64, 2);
        k_ea_gemm<<<gea, 128>>>(e_b, a_b);
    }
    {
        dim3 g1(4, NC, Bb);
        k2a_affine<<<g1, 256>>>();
        dim3 g2(4, Bb);
        k2b_chunkstart<<<g2, 256>>>(Mv0, out_Mv);
        dim3 g3(NC, Bb);
        k2c_expand<<<g3, 128>>>(out_Mv);
    }
    k_f_gemm<<<BT/64, 128>>>(f_b, p_W, p_b, out_p);
}

// round 6
// speedup vs baseline: 1.3756x; 1.2455x over previous
#include <cuda_runtime.h>
#include <cuda_bf16.h>
#include <math.h>

#define Bb   64
#define Tt   200
#define Dd   128
#define Mm   50
#define BT   (Bb*Tt)          // 12800
#define NUMQ 1000
#define NC   8                // scan chunks
#define LL   25               // Tt / NC

// ---------------- scratch ----------------
__device__ float g_k[BT*Dd];
__device__ float g_v[BT*Dd];
__device__ float g_w[BT*Mm];
__device__ float g_e[BT*Dd];
__device__ float g_a[BT*Dd];
__device__ float g_read[BT*Dd];
__device__ float g_read2[BT*Dd];
__device__ float g_Wea[Dd*2*Dd];    // [d][o]: o<128 -> e_W^T, o>=128 -> a_W^T
__device__ float g_fWt[2*Dd*Dd];    // [dd(256)][o(128)]
__device__ float g_A[Bb*NC*Mm*Dd];  // chunk affine scale   [b][ci][m][d]
__device__ float g_B[Bb*NC*Mm*Dd];  // chunk affine offset

__device__ __forceinline__ float sigmoidf_(float x){ return 1.f/(1.f+expf(-x)); }

// ---------------- K0: transpose weights ----------------
__global__ void k0_transpose(const float* __restrict__ eW,
                             const float* __restrict__ aW, const float* __restrict__ fW){
    int tid = blockIdx.x*blockDim.x + threadIdx.x;
    int nt  = gridDim.x*blockDim.x;
    for (int i=tid; i<Dd*Dd; i+=nt){
        int o=i/Dd, d=i%Dd;
        g_Wea[d*(2*Dd)+o]      = eW[i];
        g_Wea[d*(2*Dd)+Dd+o]   = aW[i];
    }
    for (int i=tid; i<Dd*2*Dd; i+=nt){ int o=i/(2*Dd), d=i%(2*Dd); g_fWt[d*Dd+o]=fW[i]; }
}

// ---------------- K1: gather k/v, w logits + softmax ----------------
__global__ __launch_bounds__(256) void k1_gather(
    const int* __restrict__ q, const int* __restrict__ r, const int* __restrict__ pid,
    const float* __restrict__ pid_emb, const float* __restrict__ k_emb,
    const float* __restrict__ v_emb, const float* __restrict__ Mk)
{
    const int tid  = threadIdx.x;
    const int lane = tid & 31;
    const int wid  = tid >> 5;
    const int row0 = blockIdx.x * 16;

    __shared__ float k_s[16][Dd];
    __shared__ float mk_s[Mm][129];
    __shared__ float wl[16][52];

    for (int i=tid; i<Mm*Dd; i+=256) mk_s[i/Dd][i%Dd] = Mk[i];

    for (int i=tid; i<16*Dd; i+=256){
        int rr = i >> 7, d = i & 127;
        int row = row0 + rr;
        int qi = q[row], ri = r[row], pi = pid[row];
        float pe = pid_emb[pi*Dd + d];
        float kk = k_emb[qi*Dd + d] + pe;
        float vv = v_emb[(qi + ri*NUMQ)*Dd + d] + pe;
        k_s[rr][d] = kk;
        g_k[row*Dd + d] = kk;
        g_v[row*Dd + d] = vv;
    }
    __syncthreads();

    for (int p=tid; p<16*Mm; p+=256){
        int rr = p/Mm, m = p - rr*Mm;
        float acc = 0.f;
        #pragma unroll 4
        for (int d=0; d<Dd; d++) acc = fmaf(mk_s[m][d], k_s[rr][d], acc);
        wl[rr][m] = acc;
    }
    __syncthreads();

    #pragma unroll
    for (int s2=0; s2<2; s2++){
        int rr  = wid*2 + s2;
        int row = row0 + rr;
        float l0 = (lane      < Mm) ? wl[rr][lane]      : -1e30f;
        float l1 = (lane + 32 < Mm) ? wl[rr][lane + 32] : -1e30f;
        float mx = fmaxf(l0, l1);
        #pragma unroll
        for (int o=16; o; o>>=1) mx = fmaxf(mx, __shfl_xor_sync(0xffffffffu, mx, o));
        float e0 = (lane      < Mm) ? expf(l0 - mx) : 0.f;
        float e1 = (lane + 32 < Mm) ? expf(l1 - mx) : 0.f;
        float ss = e0 + e1;
        #pragma unroll
        for (int o=16; o; o>>=1) ss += __shfl_xor_sync(0xffffffffu, ss, o);
        float inv = 1.f / ss;
        if (lane      < Mm) g_w[row*Mm + lane]      = e0 * inv;
        if (lane + 32 < Mm) g_w[row*Mm + lane + 32] = e1 * inv;
    }
}

// ---------------- smem-tiled GEMM: e/a (fused) ----------------
__global__ __launch_bounds__(128) void k_ea_gemm(const float* __restrict__ e_b,
                                                 const float* __restrict__ a_b)
{
    const int tid = threadIdx.x;
    const int tx  = tid & 15;
    const int ty  = tid >> 4;
    const int row0 = blockIdx.x * 64;
    const int cb   = blockIdx.y;       // 0 -> e, 1 -> a

    __shared__ float act_s[32][68];
    __shared__ float w_s[32][128];

    float acc[8][8];
    #pragma unroll
    for (int i=0;i<8;i++)
        #pragma unroll
        for (int j=0;j<8;j++) acc[i][j]=0.f;

    for (int kc=0; kc<Dd; kc+=32){
        #pragma unroll
        for (int i=0;i<4;i++){
            int lin = tid + i*128;
            int rr  = lin >> 3;
            int kg  = lin & 7;
            float4 v = *reinterpret_cast<const float4*>(&g_v[(row0+rr)*Dd + kc + kg*4]);
            act_s[kg*4+0][rr]=v.x; act_s[kg*4+1][rr]=v.y; act_s[kg*4+2][rr]=v.z; act_s[kg*4+3][rr]=v.w;
        }
        #pragma unroll
        for (int i=0;i<8;i++){
            int lin = tid + i*128;
            int kk  = lin >> 5;
            int c4  = lin & 31;
            *reinterpret_cast<float4*>(&w_s[kk][c4*4]) =
                *reinterpret_cast<const float4*>(&g_Wea[(kc+kk)*(2*Dd) + cb*Dd + c4*4]);
        }
        __syncthreads();

        #pragma unroll 4
        for (int kk=0; kk<32; kk++){
            float4 a0 = *reinterpret_cast<float4*>(&act_s[kk][ty*8]);
            float4 a1 = *reinterpret_cast<float4*>(&act_s[kk][ty*8+4]);
            float4 w0 = *reinterpret_cast<float4*>(&w_s[kk][tx*8]);
            float4 w1 = *reinterpret_cast<float4*>(&w_s[kk][tx*8+4]);
            float av[8] = {a0.x,a0.y,a0.z,a0.w,a1.x,a1.y,a1.z,a1.w};
            float wv[8] = {w0.x,w0.y,w0.z,w0.w,w1.x,w1.y,w1.z,w1.w};
            #pragma unroll
            for (int i=0;i<8;i++)
                #pragma unroll
                for (int j=0;j<8;j++) acc[i][j] = fmaf(av[i], wv[j], acc[i][j]);
        }
        __syncthreads();
    }

    const float* bias = (cb==0) ? e_b : a_b;
    float4 b0 = *reinterpret_cast<const float4*>(&bias[tx*8]);
    float4 b1 = *reinterpret_cast<const float4*>(&bias[tx*8+4]);
    float bb[8] = {b0.x,b0.y,b0.z,b0.w,b1.x,b1.y,b1.z,b1.w};
    float* dst = (cb==0) ? g_e : g_a;
    #pragma unroll
    for (int i=0;i<8;i++){
        int row = row0 + ty*8 + i;
        float o[8];
        if (cb==0){
            #pragma unroll
            for (int j=0;j<8;j++) o[j] = sigmoidf_(acc[i][j] + bb[j]);
        } else {
            #pragma unroll
            for (int j=0;j<8;j++) o[j] = tanhf(acc[i][j] + bb[j]);
        }
        *reinterpret_cast<float4*>(&dst[row*Dd + tx*8])   = make_float4(o[0],o[1],o[2],o[3]);
        *reinterpret_cast<float4*>(&dst[row*Dd + tx*8+4]) = make_float4(o[4],o[5],o[6],o[7]);
    }
}

// ---------------- K2a: per-chunk affine composition, d-quad vectorized ----------------
// grid (NC, Bb), 256 threads: lane -> d-quad (32), wg -> m in {wg, wg+8, ...} (7).
__global__ __launch_bounds__(256) void k2a_affine()
{
    const int ci   = blockIdx.x;
    const int b    = blockIdx.y;
    const int tid  = threadIdx.x;
    const int lane = tid & 31;
    const int wg   = tid >> 5;
    const int t0   = ci * LL;

    __shared__ float w_s[LL][52];
    for (int i=tid; i<LL*Mm; i+=256){
        int tt = i / Mm, m = i - tt*Mm;
        w_s[tt][m] = g_w[((size_t)b*Tt + t0 + tt)*Mm + m];
    }
    __syncthreads();

    float4 A[7], Bv[7];
    #pragma unroll
    for (int i=0;i<7;i++){ A[i]=make_float4(1.f,1.f,1.f,1.f); Bv[i]=make_float4(0.f,0.f,0.f,0.f); }

    const float4* eb4 = reinterpret_cast<const float4*>(g_e + ((size_t)b*Tt + t0)*Dd);
    const float4* ab4 = reinterpret_cast<const float4*>(g_a + ((size_t)b*Tt + t0)*Dd);

    #pragma unroll 5
    for (int tt=0; tt<LL; tt++){
        float4 ev = eb4[tt*32 + lane];
        float4 av = ab4[tt*32 + lane];
        #pragma unroll
        for (int i=0;i<7;i++){
            int m = wg + 8*i;
            if (m < Mm){
                float wv = w_s[tt][m];
                float cx = fmaf(-wv, ev.x, 1.f);
                float cy = fmaf(-wv, ev.y, 1.f);
                float cz = fmaf(-wv, ev.z, 1.f);
                float cw = fmaf(-wv, ev.w, 1.f);
                A[i].x *= cx; A[i].y *= cy; A[i].z *= cz; A[i].w *= cw;
                Bv[i].x = fmaf(cx, Bv[i].x, wv*av.x);
                Bv[i].y = fmaf(cy, Bv[i].y, wv*av.y);
                Bv[i].z = fmaf(cz, Bv[i].z, wv*av.z);
                Bv[i].w = fmaf(cw, Bv[i].w, wv*av.w);
            }
        }
    }

    size_t base = ((size_t)(b*NC + ci)*Mm)*Dd;
    #pragma unroll
    for (int i=0;i<7;i++){
        int m = wg + 8*i;
        if (m < Mm){
            *reinterpret_cast<float4*>(&g_A[base + (size_t)m*Dd + lane*4]) = A[i];
            *reinterpret_cast<float4*>(&g_B[base + (size_t)m*Dd + lane*4]) = Bv[i];
        }
    }
}

// ---------------- K2b: chunk-start states -> out_Mv at t = 0,25,...,200 ----------------
// grid (Bb), 256 threads: lane -> d-quad, wg -> m-subset of 7.
__global__ __launch_bounds__(256) void k2b_chunkstart(const float* __restrict__ Mv0,
                                                      float* __restrict__ out_Mv)
{
    const int b    = blockIdx.x;
    const int tid  = threadIdx.x;
    const int lane = tid & 31;
    const int wg   = tid >> 5;

    float4 s[7];
    #pragma unroll
    for (int i=0;i<7;i++){
        int m = wg + 8*i;
        s[i] = (m < Mm) ? *reinterpret_cast<const float4*>(&Mv0[m*Dd + lane*4])
                        : make_float4(0.f,0.f,0.f,0.f);
    }
    {
        float* outp = out_Mv + ((size_t)(b*(Tt+1)) * Mm) * Dd;
        #pragma unroll
        for (int i=0;i<7;i++){
            int m = wg + 8*i;
            if (m < Mm) __stcs(reinterpret_cast<float4*>(&outp[(size_t)m*Dd + lane*4]), s[i]);
        }
    }
    for (int ci=0; ci<NC; ci++){
        size_t base = ((size_t)(b*NC + ci)*Mm)*Dd;
        #pragma unroll
        for (int i=0;i<7;i++){
            int m = wg + 8*i;
            if (m < Mm){
                float4 A  = *reinterpret_cast<const float4*>(&g_A[base + (size_t)m*Dd + lane*4]);
                float4 Bv = *reinterpret_cast<const float4*>(&g_B[base + (size_t)m*Dd + lane*4]);
                s[i].x = fmaf(A.x, s[i].x, Bv.x);
                s[i].y = fmaf(A.y, s[i].y, Bv.y);
                s[i].z = fmaf(A.z, s[i].z, Bv.z);
                s[i].w = fmaf(A.w, s[i].w, Bv.w);
            }
        }
        float* outp = out_Mv + ((size_t)(b*(Tt+1) + (ci+1)*LL) * Mm) * Dd;
        #pragma unroll
        for (int i=0;i<7;i++){
            int m = wg + 8*i;
            if (m < Mm) __stcs(reinterpret_cast<float4*>(&outp[(size_t)m*Dd + lane*4]), s[i]);
        }
    }
}

// ---------------- K2c: expand chunks, 2-way m-split, streaming stores ----------------
// grid (NC, Bb, 2): mh = m-half. 128 threads: thread = d. mv[25] in regs.
__global__ __launch_bounds__(128) void k2c_expand(float* __restrict__ out_Mv)
{
    const int ci = blockIdx.x;
    const int b  = blockIdx.y;
    const int mh = blockIdx.z;        // 0: m in [0,25), 1: m in [25,50)
    const int d  = threadIdx.x;
    const int t0 = ci * LL;
    const int m0 = mh * 25;

    __shared__ float w_s[LL][28];
    for (int i=d; i<LL*25; i+=128){
        int tt = i / 25, mm = i - tt*25;
        w_s[tt][mm] = g_w[((size_t)b*Tt + t0 + tt)*Mm + m0 + mm];
    }
    __syncthreads();

    float mv[25];
    {
        const float* st = out_Mv + ((size_t)(b*(Tt+1) + t0) * Mm) * Dd;
        #pragma unroll
        for (int mm=0; mm<25; mm++) mv[mm] = st[(size_t)(m0+mm)*Dd + d];
    }

    const float* eb = g_e + ((size_t)b*Tt + t0)*Dd;
    const float* ab = g_a + ((size_t)b*Tt + t0)*Dd;
    float*       rb = ((mh==0) ? g_read : g_read2) + ((size_t)b*Tt + t0)*Dd;

    // tt = 0: read + update only (chunk start already stored by k2b)
    {
        float ev = eb[d], av = ab[d];
        float racc = 0.f;
        #pragma unroll
        for (int mm=0; mm<25; mm++){
            float wv = w_s[0][mm];
            racc = fmaf(wv, mv[mm], racc);
            float we = wv * ev;
            mv[mm] = fmaf(wv, av, fmaf(-we, mv[mm], mv[mm]));
        }
        rb[d] = racc;
    }
    for (int tt=1; tt<LL; tt++){
        float ev = eb[tt*Dd + d], av = ab[tt*Dd + d];
        float* outp = out_Mv + ((size_t)(b*(Tt+1) + t0 + tt) * Mm) * Dd;
        float racc = 0.f;
        #pragma unroll
        for (int mm=0; mm<25; mm++){
            float wv = w_s[tt][mm];
            float s  = mv[mm];
            racc = fmaf(wv, s, racc);
            __stcs(&outp[(size_t)(m0+mm)*Dd + d], s);
            float we = wv * ev;
            mv[mm] = fmaf(wv, av, fmaf(-we, s, s));
        }
        rb[tt*Dd + d] = racc;
    }
}

// ---------------- smem-tiled GEMM: f + p head (sums g_read + g_read2) ----------------
__global__ __launch_bounds__(128) void k_f_gemm(const float* __restrict__ f_b,
                                                const float* __restrict__ p_W,
                                                const float* __restrict__ p_b,
                                                float* __restrict__ out_p)
{
    const int tid = threadIdx.x;
    const int tx  = tid & 15;
    const int ty  = tid >> 4;
    const int row0 = blockIdx.x * 64;

    __shared__ float act_s[32][68];
    __shared__ float w_s[32][128];

    float acc[8][8];
    #pragma unroll
    for (int i=0;i<8;i++)
        #pragma unroll
        for (int j=0;j<8;j++) acc[i][j]=0.f;

    for (int kc=0; kc<2*Dd; kc+=32){
        if (kc < Dd){
            const float* src1 = g_read  + (size_t)row0*Dd + kc;
            const float* src2 = g_read2 + (size_t)row0*Dd + kc;
            #pragma unroll
            for (int i=0;i<4;i++){
                int lin = tid + i*128;
                int rr  = lin >> 3;
                int kg  = lin & 7;
                float4 v1 = *reinterpret_cast<const float4*>(&src1[rr*Dd + kg*4]);
                float4 v2 = *reinterpret_cast<const float4*>(&src2[rr*Dd + kg*4]);
                act_s[kg*4+0][rr]=v1.x+v2.x; act_s[kg*4+1][rr]=v1.y+v2.y;
                act_s[kg*4+2][rr]=v1.z+v2.z; act_s[kg*4+3][rr]=v1.w+v2.w;
            }
        } else {
            const float* src = g_k + (size_t)row0*Dd + (kc - Dd);
            #pragma unroll
            for (int i=0;i<4;i++){
                int lin = tid + i*128;
                int rr  = lin >> 3;
                int kg  = lin & 7;
                float4 v = *reinterpret_cast<const float4*>(&src[rr*Dd + kg*4]);
                act_s[kg*4+0][rr]=v.x; act_s[kg*4+1][rr]=v.y; act_s[kg*4+2][rr]=v.z; act_s[kg*4+3][rr]=v.w;
            }
        }
        #pragma unroll
        for (int i=0;i<8;i++){
            int lin = tid + i*128;
            int kk  = lin >> 5;
            int c4  = lin & 31;
            *reinterpret_cast<float4*>(&w_s[kk][c4*4]) =
                *reinterpret_cast<const float4*>(&g_fWt[(kc+kk)*Dd + c4*4]);
        }
        __syncthreads();

        #pragma unroll 4
        for (int kk=0; kk<32; kk++){
            float4 a0 = *reinterpret_cast<float4*>(&act_s[kk][ty*8]);
            float4 a1 = *reinterpret_cast<float4*>(&act_s[kk][ty*8+4]);
            float4 w0 = *reinterpret_cast<float4*>(&w_s[kk][tx*8]);
            float4 w1 = *reinterpret_cast<float4*>(&w_s[kk][tx*8+4]);
            float av[8] = {a0.x,a0.y,a0.z,a0.w,a1.x,a1.y,a1.z,a1.w};
            float wv[8] = {w0.x,w0.y,w0.z,w0.w,w1.x,w1.y,w1.z,w1.w};
            #pragma unroll
            for (int i=0;i<8;i++)
                #pragma unroll
                for (int j=0;j<8;j++) acc[i][j] = fmaf(av[i], wv[j], acc[i][j]);
        }
        __syncthreads();
    }

    float4 fb0 = *reinterpret_cast<const float4*>(&f_b[tx*8]);
    float4 fb1 = *reinterpret_cast<const float4*>(&f_b[tx*8+4]);
    float4 pw0 = *reinterpret_cast<const float4*>(&p_W[tx*8]);
    float4 pw1 = *reinterpret_cast<const float4*>(&p_W[tx*8+4]);
    float fbv[8] = {fb0.x,fb0.y,fb0.z,fb0.w,fb1.x,fb1.y,fb1.z,fb1.w};
    float pwv[8] = {pw0.x,pw0.y,pw0.z,pw0.w,pw1.x,pw1.y,pw1.z,pw1.w};

    float rs[8];
    #pragma unroll
    for (int i=0;i<8;i++){
        float s = 0.f;
        #pragma unroll
        for (int j=0;j<8;j++) s = fmaf(pwv[j], tanhf(acc[i][j] + fbv[j]), s);
        rs[i] = s;
    }
    #pragma unroll
    for (int o=1; o<16; o<<=1){
        #pragma unroll
        for (int i=0;i<8;i++) rs[i] += __shfl_xor_sync(0xffffffffu, rs[i], o);
    }
    if (tx == 0){
        float pb = p_b[0];
        #pragma unroll
        for (int i=0;i<8;i++) out_p[row0 + ty*8 + i] = sigmoidf_(rs[i] + pb);
    }
}

// ---------------- launch ----------------
extern "C" void kernel_launch(void* const* d_in, const int* in_sizes, int n_in,
                              void* d_out, int out_size)
{
    const int*   q       = (const int*)  d_in[0];
    const int*   r       = (const int*)  d_in[1];
    const int*   pid     = (const int*)  d_in[2];
    const float* pid_emb = (const float*)d_in[3];
    const float* k_emb   = (const float*)d_in[4];
    const float* v_emb   = (const float*)d_in[5];
    const float* Mk      = (const float*)d_in[6];
    const float* Mv0     = (const float*)d_in[7];
    const float* f_W     = (const float*)d_in[8];
    const float* f_b     = (const float*)d_in[9];
    const float* p_W     = (const float*)d_in[10];
    const float* p_b     = (const float*)d_in[11];
    const float* e_W     = (const float*)d_in[12];
    const float* e_b     = (const float*)d_in[13];
    const float* a_W     = (const float*)d_in[14];
    const float* a_b     = (const float*)d_in[15];

    float* out_p  = (float*)d_out;              // (64, 200)
    float* out_Mv = (float*)d_out + BT;         // (64, 201, 50, 128)

    k0_transpose<<<256, 256>>>(e_W, a_W, f_W);
    k1_gather<<<BT/16, 256>>>(q, r, pid, pid_emb, k_emb, v_emb, Mk);
    {
        dim3 gea(BT/64, 2);
        k_ea_gemm<<<gea, 128>>>(e_b, a_b);
    }
    {
        dim3 g1(NC, Bb);
        k2a_affine<<<g1, 256>>>();
        k2b_chunkstart<<<Bb, 256>>>(Mv0, out_Mv);
        dim3 g3(NC, Bb, 2);
        k2c_expand<<<g3, 128>>>(out_Mv);
    }
    k_f_gemm<<<BT/64, 128>>>(f_b, p_W, p_b, out_p);
}

// round 7
// speedup vs baseline: 1.3786x; 1.0022x over previous
#include <cuda_runtime.h>
#include <cuda_bf16.h>
#include <math.h>

#define Bb   64
#define Tt   200
#define Dd   128
#define Mm   50
#define BT   (Bb*Tt)          // 12800
#define NUMQ 1000
#define NC   8                // scan chunks
#define LL   25               // Tt / NC
#define PH   13               // k2c reduction phase length

// ---------------- scratch ----------------
__device__ float g_k[BT*Dd];
__device__ float g_v[BT*Dd];
__device__ float g_w[BT*Mm];
__device__ float g_e[BT*Dd];
__device__ float g_a[BT*Dd];
__device__ float g_read[BT*Dd];
__device__ float g_read2[BT*Dd];
__device__ float g_Wea[Dd*2*Dd];    // [d][o]: o<128 -> e_W^T, o>=128 -> a_W^T
__device__ float g_fWt[2*Dd*Dd];    // [dd(256)][o(128)]
__device__ float g_A[Bb*NC*Mm*Dd];  // chunk affine scale   [b][ci][m][d]
__device__ float g_B[Bb*NC*Mm*Dd];  // chunk affine offset

__device__ __forceinline__ float sigmoidf_(float x){ return 1.f/(1.f+expf(-x)); }

// ---------------- K0: transpose weights ----------------
__global__ void k0_transpose(const float* __restrict__ eW,
                             const float* __restrict__ aW, const float* __restrict__ fW){
    int tid = blockIdx.x*blockDim.x + threadIdx.x;
    int nt  = gridDim.x*blockDim.x;
    for (int i=tid; i<Dd*Dd; i+=nt){
        int o=i/Dd, d=i%Dd;
        g_Wea[d*(2*Dd)+o]      = eW[i];
        g_Wea[d*(2*Dd)+Dd+o]   = aW[i];
    }
    for (int i=tid; i<Dd*2*Dd; i+=nt){ int o=i/(2*Dd), d=i%(2*Dd); g_fWt[d*Dd+o]=fW[i]; }
}

// ---------------- K1: gather k/v, w logits + softmax ----------------
__global__ __launch_bounds__(256) void k1_gather(
    const int* __restrict__ q, const int* __restrict__ r, const int* __restrict__ pid,
    const float* __restrict__ pid_emb, const float* __restrict__ k_emb,
    const float* __restrict__ v_emb, const float* __restrict__ Mk)
{
    const int tid  = threadIdx.x;
    const int lane = tid & 31;
    const int wid  = tid >> 5;
    const int row0 = blockIdx.x * 16;

    __shared__ float k_s[16][Dd];
    __shared__ float mk_s[Mm][129];
    __shared__ float wl[16][52];

    for (int i=tid; i<Mm*Dd; i+=256) mk_s[i/Dd][i%Dd] = Mk[i];

    for (int i=tid; i<16*Dd; i+=256){
        int rr = i >> 7, d = i & 127;
        int row = row0 + rr;
        int qi = q[row], ri = r[row], pi = pid[row];
        float pe = pid_emb[pi*Dd + d];
        float kk = k_emb[qi*Dd + d] + pe;
        float vv = v_emb[(qi + ri*NUMQ)*Dd + d] + pe;
        k_s[rr][d] = kk;
        g_k[row*Dd + d] = kk;
        g_v[row*Dd + d] = vv;
    }
    __syncthreads();

    for (int p=tid; p<16*Mm; p+=256){
        int rr = p/Mm, m = p - rr*Mm;
        float acc = 0.f;
        #pragma unroll 4
        for (int d=0; d<Dd; d++) acc = fmaf(mk_s[m][d], k_s[rr][d], acc);
        wl[rr][m] = acc;
    }
    __syncthreads();

    #pragma unroll
    for (int s2=0; s2<2; s2++){
        int rr  = wid*2 + s2;
        int row = row0 + rr;
        float l0 = (lane      < Mm) ? wl[rr][lane]      : -1e30f;
        float l1 = (lane + 32 < Mm) ? wl[rr][lane + 32] : -1e30f;
        float mx = fmaxf(l0, l1);
        #pragma unroll
        for (int o=16; o; o>>=1) mx = fmaxf(mx, __shfl_xor_sync(0xffffffffu, mx, o));
        float e0 = (lane      < Mm) ? expf(l0 - mx) : 0.f;
        float e1 = (lane + 32 < Mm) ? expf(l1 - mx) : 0.f;
        float ss = e0 + e1;
        #pragma unroll
        for (int o=16; o; o>>=1) ss += __shfl_xor_sync(0xffffffffu, ss, o);
        float inv = 1.f / ss;
        if (lane      < Mm) g_w[row*Mm + lane]      = e0 * inv;
        if (lane + 32 < Mm) g_w[row*Mm + lane + 32] = e1 * inv;
    }
}

// ---------------- smem-tiled GEMM: e/a (fused) ----------------
__global__ __launch_bounds__(128) void k_ea_gemm(const float* __restrict__ e_b,
                                                 const float* __restrict__ a_b)
{
    const int tid = threadIdx.x;
    const int tx  = tid & 15;
    const int ty  = tid >> 4;
    const int row0 = blockIdx.x * 64;
    const int cb   = blockIdx.y;       // 0 -> e, 1 -> a

    __shared__ float act_s[32][68];
    __shared__ float w_s[32][128];

    float acc[8][8];
    #pragma unroll
    for (int i=0;i<8;i++)
        #pragma unroll
        for (int j=0;j<8;j++) acc[i][j]=0.f;

    for (int kc=0; kc<Dd; kc+=32){
        #pragma unroll
        for (int i=0;i<4;i++){
            int lin = tid + i*128;
            int rr  = lin >> 3;
            int kg  = lin & 7;
            float4 v = *reinterpret_cast<const float4*>(&g_v[(row0+rr)*Dd + kc + kg*4]);
            act_s[kg*4+0][rr]=v.x; act_s[kg*4+1][rr]=v.y; act_s[kg*4+2][rr]=v.z; act_s[kg*4+3][rr]=v.w;
        }
        #pragma unroll
        for (int i=0;i<8;i++){
            int lin = tid + i*128;
            int kk  = lin >> 5;
            int c4  = lin & 31;
            *reinterpret_cast<float4*>(&w_s[kk][c4*4]) =
                *reinterpret_cast<const float4*>(&g_Wea[(kc+kk)*(2*Dd) + cb*Dd + c4*4]);
        }
        __syncthreads();

        #pragma unroll 4
        for (int kk=0; kk<32; kk++){
            float4 a0 = *reinterpret_cast<float4*>(&act_s[kk][ty*8]);
            float4 a1 = *reinterpret_cast<float4*>(&act_s[kk][ty*8+4]);
            float4 w0 = *reinterpret_cast<float4*>(&w_s[kk][tx*8]);
            float4 w1 = *reinterpret_cast<float4*>(&w_s[kk][tx*8+4]);
            float av[8] = {a0.x,a0.y,a0.z,a0.w,a1.x,a1.y,a1.z,a1.w};
            float wv[8] = {w0.x,w0.y,w0.z,w0.w,w1.x,w1.y,w1.z,w1.w};
            #pragma unroll
            for (int i=0;i<8;i++)
                #pragma unroll
                for (int j=0;j<8;j++) acc[i][j] = fmaf(av[i], wv[j], acc[i][j]);
        }
        __syncthreads();
    }

    const float* bias = (cb==0) ? e_b : a_b;
    float4 b0 = *reinterpret_cast<const float4*>(&bias[tx*8]);
    float4 b1 = *reinterpret_cast<const float4*>(&bias[tx*8+4]);
    float bb[8] = {b0.x,b0.y,b0.z,b0.w,b1.x,b1.y,b1.z,b1.w};
    float* dst = (cb==0) ? g_e : g_a;
    #pragma unroll
    for (int i=0;i<8;i++){
        int row = row0 + ty*8 + i;
        float o[8];
        if (cb==0){
            #pragma unroll
            for (int j=0;j<8;j++) o[j] = sigmoidf_(acc[i][j] + bb[j]);
        } else {
            #pragma unroll
            for (int j=0;j<8;j++) o[j] = tanhf(acc[i][j] + bb[j]);
        }
        *reinterpret_cast<float4*>(&dst[row*Dd + tx*8])   = make_float4(o[0],o[1],o[2],o[3]);
        *reinterpret_cast<float4*>(&dst[row*Dd + tx*8+4]) = make_float4(o[4],o[5],o[6],o[7]);
    }
}

// ---------------- K2a: per-chunk affine composition, d-quad + m-half split ----------------
// grid (NC, Bb, 2), 256 threads: lane -> d-quad, wg -> local m in {wg, wg+8, ...} (<=4).
__global__ __launch_bounds__(256) void k2a_affine()
{
    const int ci   = blockIdx.x;
    const int b    = blockIdx.y;
    const int mh   = blockIdx.z;
    const int tid  = threadIdx.x;
    const int lane = tid & 31;
    const int wg   = tid >> 5;
    const int t0   = ci * LL;
    const int m0   = mh * 25;

    __shared__ float w_s[LL][28];
    for (int i=tid; i<LL*25; i+=256){
        int tt = i / 25, mm = i - tt*25;
        w_s[tt][mm] = g_w[((size_t)b*Tt + t0 + tt)*Mm + m0 + mm];
    }
    __syncthreads();

    float4 A[4], Bv[4];
    #pragma unroll
    for (int i=0;i<4;i++){ A[i]=make_float4(1.f,1.f,1.f,1.f); Bv[i]=make_float4(0.f,0.f,0.f,0.f); }

    const float4* eb4 = reinterpret_cast<const float4*>(g_e + ((size_t)b*Tt + t0)*Dd);
    const float4* ab4 = reinterpret_cast<const float4*>(g_a + ((size_t)b*Tt + t0)*Dd);

    #pragma unroll 5
    for (int tt=0; tt<LL; tt++){
        float4 ev = eb4[tt*32 + lane];
        float4 av = ab4[tt*32 + lane];
        #pragma unroll
        for (int i=0;i<4;i++){
            int mm = wg + 8*i;
            if (mm < 25){
                float wv = w_s[tt][mm];
                float cx = fmaf(-wv, ev.x, 1.f);
                float cy = fmaf(-wv, ev.y, 1.f);
                float cz = fmaf(-wv, ev.z, 1.f);
                float cw = fmaf(-wv, ev.w, 1.f);
                A[i].x *= cx; A[i].y *= cy; A[i].z *= cz; A[i].w *= cw;
                Bv[i].x = fmaf(cx, Bv[i].x, wv*av.x);
                Bv[i].y = fmaf(cy, Bv[i].y, wv*av.y);
                Bv[i].z = fmaf(cz, Bv[i].z, wv*av.z);
                Bv[i].w = fmaf(cw, Bv[i].w, wv*av.w);
            }
        }
    }

    size_t base = ((size_t)(b*NC + ci)*Mm)*Dd;
    #pragma unroll
    for (int i=0;i<4;i++){
        int mm = wg + 8*i;
        if (mm < 25){
            *reinterpret_cast<float4*>(&g_A[base + (size_t)(m0+mm)*Dd + lane*4]) = A[i];
            *reinterpret_cast<float4*>(&g_B[base + (size_t)(m0+mm)*Dd + lane*4]) = Bv[i];
        }
    }
}

// ---------------- K2b: chunk-start states -> out_Mv at t = 0,25,...,200 ----------------
__global__ __launch_bounds__(256) void k2b_chunkstart(const float* __restrict__ Mv0,
                                                      float* __restrict__ out_Mv)
{
    const int b    = blockIdx.x;
    const int tid  = threadIdx.x;
    const int lane = tid & 31;
    const int wg   = tid >> 5;

    float4 s[7];
    #pragma unroll
    for (int i=0;i<7;i++){
        int m = wg + 8*i;
        s[i] = (m < Mm) ? *reinterpret_cast<const float4*>(&Mv0[m*Dd + lane*4])
                        : make_float4(0.f,0.f,0.f,0.f);
    }
    {
        float* outp = out_Mv + ((size_t)(b*(Tt+1)) * Mm) * Dd;
        #pragma unroll
        for (int i=0;i<7;i++){
            int m = wg + 8*i;
            if (m < Mm) __stcs(reinterpret_cast<float4*>(&outp[(size_t)m*Dd + lane*4]), s[i]);
        }
    }
    for (int ci=0; ci<NC; ci++){
        size_t base = ((size_t)(b*NC + ci)*Mm)*Dd;
        #pragma unroll
        for (int i=0;i<7;i++){
            int m = wg + 8*i;
            if (m < Mm){
                float4 A  = *reinterpret_cast<const float4*>(&g_A[base + (size_t)m*Dd + lane*4]);
                float4 Bv = *reinterpret_cast<const float4*>(&g_B[base + (size_t)m*Dd + lane*4]);
                s[i].x = fmaf(A.x, s[i].x, Bv.x);
                s[i].y = fmaf(A.y, s[i].y, Bv.y);
                s[i].z = fmaf(A.z, s[i].z, Bv.z);
                s[i].w = fmaf(A.w, s[i].w, Bv.w);
            }
        }
        float* outp = out_Mv + ((size_t)(b*(Tt+1) + (ci+1)*LL) * Mm) * Dd;
        #pragma unroll
        for (int i=0;i<7;i++){
            int m = wg + 8*i;
            if (m < Mm) __stcs(reinterpret_cast<float4*>(&outp[(size_t)m*Dd + lane*4]), s[i]);
        }
    }
}

// ---------------- K2c: expand chunks, d-quad STG.128, phase-reduced read ----------------
// grid (NC, Bb, 2): mh = m-half. 128 threads (4 warps): lane -> d-quad,
// warp wg owns local mm in {wg, wg+4, ...} (<=7). mv[7] float4.
__global__ __launch_bounds__(128) void k2c_expand(float* __restrict__ out_Mv)
{
    const int ci = blockIdx.x;
    const int b  = blockIdx.y;
    const int mh = blockIdx.z;
    const int tid  = threadIdx.x;
    const int lane = tid & 31;
    const int wg   = tid >> 5;
    const int t0 = ci * LL;
    const int m0 = mh * 25;

    __shared__ float w_s[LL][28];
    __shared__ float part[4][PH][Dd];     // per-warp read partials for one phase

    for (int i=tid; i<LL*25; i+=128){
        int tt = i / 25, mm = i - tt*25;
        w_s[tt][mm] = g_w[((size_t)b*Tt + t0 + tt)*Mm + m0 + mm];
    }
    __syncthreads();

    float4 mv[7];
    {
        const float* st = out_Mv + ((size_t)(b*(Tt+1) + t0) * Mm) * Dd;
        #pragma unroll
        for (int i=0;i<7;i++){
            int mm = wg + 4*i;
            mv[i] = (mm < 25) ? *reinterpret_cast<const float4*>(&st[(size_t)(m0+mm)*Dd + lane*4])
                              : make_float4(0.f,0.f,0.f,0.f);
        }
    }

    const float4* eb4 = reinterpret_cast<const float4*>(g_e + ((size_t)b*Tt + t0)*Dd);
    const float4* ab4 = reinterpret_cast<const float4*>(g_a + ((size_t)b*Tt + t0)*Dd);
    float*        rb  = ((mh==0) ? g_read : g_read2) + ((size_t)b*Tt + t0)*Dd;

    for (int ph=0; ph<2; ph++){
        const int ttA = ph*PH;
        const int ttB = (ph==0) ? PH : LL;

        for (int tt=ttA; tt<ttB; tt++){
            float4 ev = eb4[tt*32 + lane];
            float4 av = ab4[tt*32 + lane];
            float* outp = out_Mv + ((size_t)(b*(Tt+1) + t0 + tt) * Mm) * Dd;
            float4 racc = make_float4(0.f,0.f,0.f,0.f);
            #pragma unroll
            for (int i=0;i<7;i++){
                int mm = wg + 4*i;
                if (mm < 25){
                    float wv = w_s[tt][mm];
                    float4 s = mv[i];
                    racc.x = fmaf(wv, s.x, racc.x);
                    racc.y = fmaf(wv, s.y, racc.y);
                    racc.z = fmaf(wv, s.z, racc.z);
                    racc.w = fmaf(wv, s.w, racc.w);
                    if (tt > 0)
                        __stcs(reinterpret_cast<float4*>(&outp[(size_t)(m0+mm)*Dd + lane*4]), s);
                    float wex = wv * ev.x, wey = wv * ev.y, wez = wv * ev.z, wew = wv * ev.w;
                    mv[i].x = fmaf(wv, av.x, fmaf(-wex, s.x, s.x));
                    mv[i].y = fmaf(wv, av.y, fmaf(-wey, s.y, s.y));
                    mv[i].z = fmaf(wv, av.z, fmaf(-wez, s.z, s.z));
                    mv[i].w = fmaf(wv, av.w, fmaf(-wew, s.w, s.w));
                }
            }
            *reinterpret_cast<float4*>(&part[wg][tt-ttA][lane*4]) = racc;
        }
        __syncthreads();
        // reduce this phase's read partials: threads cover (tt, lane) pairs
        const int nt = ttB - ttA;
        for (int idx=tid; idx<nt*32; idx+=128){
            int tt = idx >> 5, l = idx & 31;
            float4 p0 = *reinterpret_cast<float4*>(&part[0][tt][l*4]);
            float4 p1 = *reinterpret_cast<float4*>(&part[1][tt][l*4]);
            float4 p2 = *reinterpret_cast<float4*>(&part[2][tt][l*4]);
            float4 p3 = *reinterpret_cast<float4*>(&part[3][tt][l*4]);
            float4 rs = make_float4(p0.x+p1.x+p2.x+p3.x, p0.y+p1.y+p2.y+p3.y,
                                    p0.z+p1.z+p2.z+p3.z, p0.w+p1.w+p2.w+p3.w);
            *reinterpret_cast<float4*>(&rb[(size_t)(ttA+tt)*Dd + l*4]) = rs;
        }
        __syncthreads();
    }
}

// ---------------- smem-tiled GEMM: f + p head (sums g_read + g_read2) ----------------
__global__ __launch_bounds__(128) void k_f_gemm(const float* __restrict__ f_b,
                                                const float* __restrict__ p_W,
                                                const float* __restrict__ p_b,
                                                float* __restrict__ out_p)
{
    const int tid = threadIdx.x;
    const int tx  = tid & 15;
    const int ty  = tid >> 4;
    const int row0 = blockIdx.x * 64;

    __shared__ float act_s[32][68];
    __shared__ float w_s[32][128];

    float acc[8][8];
    #pragma unroll
    for (int i=0;i<8;i++)
        #pragma unroll
        for (int j=0;j<8;j++) acc[i][j]=0.f;

    for (int kc=0; kc<2*Dd; kc+=32){
        if (kc < Dd){
            const float* src1 = g_read  + (size_t)row0*Dd + kc;
            const float* src2 = g_read2 + (size_t)row0*Dd + kc;
            #pragma unroll
            for (int i=0;i<4;i++){
                int lin = tid + i*128;
                int rr  = lin >> 3;
                int kg  = lin & 7;
                float4 v1 = *reinterpret_cast<const float4*>(&src1[rr*Dd + kg*4]);
                float4 v2 = *reinterpret_cast<const float4*>(&src2[rr*Dd + kg*4]);
                act_s[kg*4+0][rr]=v1.x+v2.x; act_s[kg*4+1][rr]=v1.y+v2.y;
                act_s[kg*4+2][rr]=v1.z+v2.z; act_s[kg*4+3][rr]=v1.w+v2.w;
            }
        } else {
            const float* src = g_k + (size_t)row0*Dd + (kc - Dd);
            #pragma unroll
            for (int i=0;i<4;i++){
                int lin = tid + i*128;
                int rr  = lin >> 3;
                int kg  = lin & 7;
                float4 v = *reinterpret_cast<const float4*>(&src[rr*Dd + kg*4]);
                act_s[kg*4+0][rr]=v.x; act_s[kg*4+1][rr]=v.y; act_s[kg*4+2][rr]=v.z; act_s[kg*4+3][rr]=v.w;
            }
        }
        #pragma unroll
        for (int i=0;i<8;i++){
            int lin = tid + i*128;
            int kk  = lin >> 5;
            int c4  = lin & 31;
            *reinterpret_cast<float4*>(&w_s[kk][c4*4]) =
                *reinterpret_cast<const float4*>(&g_fWt[(kc+kk)*Dd + c4*4]);
        }
        __syncthreads();

        #pragma unroll 4
        for (int kk=0; kk<32; kk++){
            float4 a0 = *reinterpret_cast<float4*>(&act_s[kk][ty*8]);
            float4 a1 = *reinterpret_cast<float4*>(&act_s[kk][ty*8+4]);
            float4 w0 = *reinterpret_cast<float4*>(&w_s[kk][tx*8]);
            float4 w1 = *reinterpret_cast<float4*>(&w_s[kk][tx*8+4]);
            float av[8] = {a0.x,a0.y,a0.z,a0.w,a1.x,a1.y,a1.z,a1.w};
            float wv[8] = {w0.x,w0.y,w0.z,w0.w,w1.x,w1.y,w1.z,w1.w};
            #pragma unroll
            for (int i=0;i<8;i++)
                #pragma unroll
                for (int j=0;j<8;j++) acc[i][j] = fmaf(av[i], wv[j], acc[i][j]);
        }
        __syncthreads();
    }

    float4 fb0 = *reinterpret_cast<const float4*>(&f_b[tx*8]);
    float4 fb1 = *reinterpret_cast<const float4*>(&f_b[tx*8+4]);
    float4 pw0 = *reinterpret_cast<const float4*>(&p_W[tx*8]);
    float4 pw1 = *reinterpret_cast<const float4*>(&p_W[tx*8+4]);
    float fbv[8] = {fb0.x,fb0.y,fb0.z,fb0.w,fb1.x,fb1.y,fb1.z,fb1.w};
    float pwv[8] = {pw0.x,pw0.y,pw0.z,pw0.w,pw1.x,pw1.y,pw1.z,pw1.w};

    float rs[8];
    #pragma unroll
    for (int i=0;i<8;i++){
        float s = 0.f;
        #pragma unroll
        for (int j=0;j<8;j++) s = fmaf(pwv[j], tanhf(acc[i][j] + fbv[j]), s);
        rs[i] = s;
    }
    #pragma unroll
    for (int o=1; o<16; o<<=1){
        #pragma unroll
        for (int i=0;i<8;i++) rs[i] += __shfl_xor_sync(0xffffffffu, rs[i], o);
    }
    if (tx == 0){
        float pb = p_b[0];
        #pragma unroll
        for (int i=0;i<8;i++) out_p[row0 + ty*8 + i] = sigmoidf_(rs[i] + pb);
    }
}

// ---------------- launch ----------------
extern "C" void kernel_launch(void* const* d_in, const int* in_sizes, int n_in,
                              void* d_out, int out_size)
{
    const int*   q       = (const int*)  d_in[0];
    const int*   r       = (const int*)  d_in[1];
    const int*   pid     = (const int*)  d_in[2];
    const float* pid_emb = (const float*)d_in[3];
    const float* k_emb   = (const float*)d_in[4];
    const float* v_emb   = (const float*)d_in[5];
    const float* Mk      = (const float*)d_in[6];
    const float* Mv0     = (const float*)d_in[7];
    const float* f_W     = (const float*)d_in[8];
    const float* f_b     = (const float*)d_in[9];
    const float* p_W     = (const float*)d_in[10];
    const float* p_b     = (const float*)d_in[11];
    const float* e_W     = (const float*)d_in[12];
    const float* e_b     = (const float*)d_in[13];
    const float* a_W     = (const float*)d_in[14];
    const float* a_b     = (const float*)d_in[15];

    float* out_p  = (float*)d_out;              // (64, 200)
    float* out_Mv = (float*)d_out + BT;         // (64, 201, 50, 128)

    k0_transpose<<<256, 256>>>(e_W, a_W, f_W);
    k1_gather<<<BT/16, 256>>>(q, r, pid, pid_emb, k_emb, v_emb, Mk);
    {
        dim3 gea(BT/64, 2);
        k_ea_gemm<<<gea, 128>>>(e_b, a_b);
    }
    {
        dim3 g1(NC, Bb, 2);
        k2a_affine<<<g1, 256>>>();
        k2b_chunkstart<<<Bb, 256>>>(Mv0, out_Mv);
        dim3 g3(NC, Bb, 2);
        k2c_expand<<<g3, 128>>>(out_Mv);
    }
    k_f_gemm<<<BT/64, 128>>>(f_b, p_W, p_b, out_p);
}